// round 6
// baseline (speedup 1.0000x reference)
#include <cuda_runtime.h>
#include <math.h>

#define NN 20000
#define EE 320000
#define LD 128
#define MAXIT 10

// ---------------- device scratch ----------------
__device__ __align__(16) float g_h[NN * LD];          // hidden state
__device__ __align__(16) float g_ab[NN * 2 * LD];     // [a | b] per node
__device__ __align__(16) float g_agg[NN * LD];        // aggregated messages
__device__ __align__(16) float g_pre[2ull * NN * 2 * LD]; // precomputed z_r @ [W1_top|W2_top]
__device__ __align__(16) float g_u[NN];
__device__ __align__(16) float g_v[NN];
__device__ __align__(16) float g_alpha[EE];
__device__ int g_mx[NN];                              // max alpha bits over incident edges
__device__ unsigned long long g_pack[NN];             // (alpha_bits<<32)|(EE-1-e) max
__device__ int g_deg[NN];
__device__ int g_off[NN];
__device__ int g_cursor[NN];
__device__ int g_csrc[EE];                            // CSR-by-dst source ids

#define FMA2(d, a, b) asm("fma.rn.f32x2 %0, %1, %2, %0;" : "+l"(d) : "l"(a), "l"(b))

// ---------------- init ----------------
__global__ void init_kernel(const float* __restrict__ s) {
    int idx = blockIdx.x * blockDim.x + threadIdx.x;
    if (idx < NN * LD) g_h[idx] = 0.f;
    if (idx < NN) {
        g_deg[idx] = 0;
        g_mx[idx] = (s[idx] > 0.f) ? 0x3f800000 : 0;  // reach(iter0) = s
        g_pack[idx] = 0ull;
    }
}

// ---------------- CSR build (by dst) ----------------
__global__ void deg_kernel(const int* __restrict__ dst) {
    int e = blockIdx.x * blockDim.x + threadIdx.x;
    if (e < EE) atomicAdd(&g_deg[dst[e]], 1);
}

__global__ void scan_kernel() {  // single block, 1024 threads
    __shared__ int part[1024];
    int t = threadIdx.x;
    const int chunk = (NN + 1023) / 1024;
    int b0 = t * chunk;
    int acc = 0;
    for (int i = 0; i < chunk; i++) {
        int idx = b0 + i;
        if (idx < NN) acc += g_deg[idx];
    }
    part[t] = acc;
    __syncthreads();
    for (int o = 1; o < 1024; o <<= 1) {
        int v = (t >= o) ? part[t - o] : 0;
        __syncthreads();
        part[t] += v;
        __syncthreads();
    }
    int run = (t == 0) ? 0 : part[t - 1];
    for (int i = 0; i < chunk; i++) {
        int idx = b0 + i;
        if (idx < NN) {
            g_off[idx] = run;
            g_cursor[idx] = run;
            run += g_deg[idx];
        }
    }
}

__global__ void fill_kernel(const int* __restrict__ src, const int* __restrict__ dst) {
    int e = blockIdx.x * blockDim.x + threadIdx.x;
    if (e < EE) {
        int p = atomicAdd(&g_cursor[dst[e]], 1);
        g_csrc[p] = src[e];
    }
}

// ---------------- unified f32x2 GEMM ----------------
// MODE 0: pre[r] = z_r(pos) @ [W1_top|W2_top]    grid (157,4,2)
// MODE 1: ab = h @ [W1_bot|W2_bot] + pre[reach]  grid (157,4)
// MODE 2: h = relu(agg @ Wout + bout)            grid (157,2)
template <int MODE>
__global__ __launch_bounds__(256) void gemm_kernel(
    const float* __restrict__ B1, const float* __restrict__ B2,
    const float* __restrict__ pos, const float* __restrict__ We,
    const float* __restrict__ be, const float* __restrict__ bias) {
    __shared__ float As[16][132];
    __shared__ float Bs[16][128];  // column-duplicated: Bs[k][2j],Bs[k][2j+1] = B[k][j]
    int m0 = blockIdx.x * 128;
    int j0 = blockIdx.y * 64;
    int r = (MODE == 0) ? (int)blockIdx.z : 0;
    const float* Bptr;
    int jb;
    if (MODE == 2) { Bptr = B1; jb = j0; }
    else if (j0 < 128) { Bptr = B1; jb = j0; }
    else { Bptr = B2; jb = j0 - 128; }
    int t = threadIdx.x, tx = t & 15, ty = t >> 4;
    unsigned long long c2[4][4] = {};

    for (int kt = 0; kt < 128; kt += 16) {
#pragma unroll
        for (int rr = 0; rr < 2; rr++) {
            int f = t + rr * 256;
            int mloc = f >> 2, k4 = (f & 3) * 4;
            int m = m0 + mloc;
            float4 av = make_float4(0.f, 0.f, 0.f, 0.f);
            if (m < NN) {
                if (MODE == 0) {
                    float p = pos[m];
                    float rf = (float)r;
                    float4 w0 = *(const float4*)(We + kt + k4);
                    float4 w1 = *(const float4*)(We + 128 + kt + k4);
                    float4 b0 = *(const float4*)(be + kt + k4);
                    av.x = fmaxf(fmaf(p, w0.x, fmaf(rf, w1.x, b0.x)), 0.f);
                    av.y = fmaxf(fmaf(p, w0.y, fmaf(rf, w1.y, b0.y)), 0.f);
                    av.z = fmaxf(fmaf(p, w0.z, fmaf(rf, w1.z, b0.z)), 0.f);
                    av.w = fmaxf(fmaf(p, w0.w, fmaf(rf, w1.w, b0.w)), 0.f);
                } else if (MODE == 1) {
                    av = *(const float4*)(g_h + (size_t)m * 128 + kt + k4);
                } else {
                    av = *(const float4*)(g_agg + (size_t)m * 128 + kt + k4);
                }
            }
            As[k4 + 0][mloc] = av.x;
            As[k4 + 1][mloc] = av.y;
            As[k4 + 2][mloc] = av.z;
            As[k4 + 3][mloc] = av.w;
        }
        {
            int kk = t >> 4, jg = t & 15;
            float4 b = *(const float4*)(Bptr + (size_t)(kt + kk) * 128 + jb + jg * 4);
            *(float4*)&Bs[kk][jg * 8] = make_float4(b.x, b.x, b.y, b.y);
            *(float4*)&Bs[kk][jg * 8 + 4] = make_float4(b.z, b.z, b.w, b.w);
        }
        __syncthreads();
#pragma unroll
        for (int k = 0; k < 16; k++) {
            ulonglong2 aA = *(const ulonglong2*)&As[k][ty * 8];
            ulonglong2 aB = *(const ulonglong2*)&As[k][ty * 8 + 4];
            ulonglong2 bA = *(const ulonglong2*)&Bs[k][tx * 8];
            ulonglong2 bB = *(const ulonglong2*)&Bs[k][tx * 8 + 4];
            unsigned long long ap[4] = {aA.x, aA.y, aB.x, aB.y};
            unsigned long long bd[4] = {bA.x, bA.y, bB.x, bB.y};
#pragma unroll
            for (int p = 0; p < 4; p++)
#pragma unroll
                for (int j = 0; j < 4; j++) FMA2(c2[p][j], ap[p], bd[j]);
        }
        __syncthreads();
    }

    // epilogue: each p covers rows m0+ty*8+2p (lo) and +2p+1 (hi)
#pragma unroll
    for (int p = 0; p < 4; p++) {
        int m = m0 + ty * 8 + 2 * p;
        union { unsigned long long u; float2 f; } cv;
        float4 lo, hi;
        cv.u = c2[p][0]; lo.x = cv.f.x; hi.x = cv.f.y;
        cv.u = c2[p][1]; lo.y = cv.f.x; hi.y = cv.f.y;
        cv.u = c2[p][2]; lo.z = cv.f.x; hi.z = cv.f.y;
        cv.u = c2[p][3]; lo.w = cv.f.x; hi.w = cv.f.y;
#pragma unroll
        for (int q = 0; q < 2; q++) {
            int mm = m + q;
            if (mm >= NN) continue;
            float4 v = q ? hi : lo;
            int jc = j0 + tx * 4;
            if (MODE == 0) {
                *(float4*)(g_pre + ((size_t)r * NN + mm) * 256 + jc) = v;
            } else if (MODE == 1) {
                int sel = (__int_as_float(g_mx[mm]) >= 0.4f) ? 1 : 0;
                float4 pr = *(const float4*)(g_pre + ((size_t)sel * NN + mm) * 256 + jc);
                v.x += pr.x; v.y += pr.y; v.z += pr.z; v.w += pr.w;
                *(float4*)(g_ab + (size_t)mm * 256 + jc) = v;
            } else {
                float4 bb = *(const float4*)(bias + jc);
                v.x = fmaxf(v.x + bb.x, 0.f);
                v.y = fmaxf(v.y + bb.y, 0.f);
                v.z = fmaxf(v.z + bb.z, 0.f);
                v.w = fmaxf(v.w + bb.w, 0.f);
                *(float4*)(g_h + (size_t)mm * 128 + jc) = v;
            }
        }
    }
}

// ---------------- aggregate: agg[n] = relu(max_in a[src] + b[n] + bmsg) ----------------
__global__ void aggregate_kernel(const float* __restrict__ bmsg) {
    int n = blockIdx.x;
    int l = threadIdx.x;
    int beg = g_off[n];
    int d = g_deg[n];
    float out = 0.f;
    if (d > 0) {
        float s = -3.4e38f;
        for (int p = 0; p < d; p++) {
            int sn = g_csrc[beg + p];
            s = fmaxf(s, g_ab[(size_t)sn * 256 + l]);
        }
        out = fmaxf(s + g_ab[(size_t)n * 256 + 128 + l] + bmsg[l], 0.f);
    }
    g_agg[(size_t)n * 128 + l] = out;
}

// ---------------- decoder dots + mx reset ----------------
__global__ void uv_kernel(const float* __restrict__ Wdec) {
    int gt = blockIdx.x * blockDim.x + threadIdx.x;
    int w = gt >> 5, lane = gt & 31;
    if (w >= NN) return;
    float4 hv = ((const float4*)(g_h + (size_t)w * 128))[lane];
    float4 w1 = ((const float4*)Wdec)[lane];
    float4 w2 = ((const float4*)(Wdec + 128))[lane];
    float pu = hv.x * w1.x + hv.y * w1.y + hv.z * w1.z + hv.w * w1.w;
    float pv = hv.x * w2.x + hv.y * w2.y + hv.z * w2.z + hv.w * w2.w;
#pragma unroll
    for (int o = 16; o; o >>= 1) {
        pu += __shfl_down_sync(0xffffffffu, pu, o);
        pv += __shfl_down_sync(0xffffffffu, pv, o);
    }
    if (lane == 0) {
        g_u[w] = pu;
        g_v[w] = pv;
        g_mx[w] = 0;  // reset for this iteration's alpha pass
    }
}

// ---------------- edge alpha + incident-max ----------------
__global__ void alpha_kernel(const int* __restrict__ src, const int* __restrict__ dst,
                             const float* __restrict__ bdec, float* __restrict__ preds_out) {
    int e = blockIdx.x * blockDim.x + threadIdx.x;
    if (e >= EE) return;
    int sn = src[e], dn = dst[e];
    float x = g_u[sn] + g_v[dn] + bdec[0];
    float al = 1.f / (1.f + expf(-x));
    preds_out[e] = al;
    g_alpha[e] = al;
    int bits = __float_as_int(al);  // al >= 0, bit order == float order
    atomicMax(&g_mx[sn], bits);
    atomicMax(&g_mx[dn], bits);
}

// ---------------- parents: single packed atomicMax pass ----------------
__global__ void pack_kernel(const int* __restrict__ dst) {
    int e = blockIdx.x * blockDim.x + threadIdx.x;
    if (e >= EE) return;
    unsigned long long p =
        ((unsigned long long)(unsigned)__float_as_int(g_alpha[e]) << 32) |
        (unsigned)(EE - 1 - e);  // tie -> larger low bits -> smaller e (first occurrence)
    atomicMax(&g_pack[dst[e]], p);
}

__global__ void output_kernel(const int* __restrict__ src, float* __restrict__ out_reach,
                              float* __restrict__ out_par) {
    int n = blockIdx.x * blockDim.x + threadIdx.x;
    if (n >= NN) return;
    out_reach[n] = (__int_as_float(g_mx[n]) >= 0.4f) ? 1.f : 0.f;
    unsigned long long p = g_pack[n];
    if (p != 0ull) {
        int e = EE - 1 - (int)(p & 0xffffffffu);
        out_par[n] = (float)src[e];
    } else {
        out_par[n] = (float)n;
    }
}

// ---------------- launch ----------------
extern "C" void kernel_launch(void* const* d_in, const int* in_sizes, int n_in,
                              void* d_out, int out_size) {
    const float* pos  = (const float*)d_in[0];
    const float* s    = (const float*)d_in[1];
    const int*   ei   = (const int*)d_in[2];
    const float* Wenc = (const float*)d_in[3];
    const float* benc = (const float*)d_in[4];
    const float* W1   = (const float*)d_in[5];
    const float* W2   = (const float*)d_in[6];
    const float* bmsg = (const float*)d_in[7];
    const float* Wout = (const float*)d_in[8];
    const float* bout = (const float*)d_in[9];
    const float* Wdec = (const float*)d_in[10];
    const float* bdec = (const float*)d_in[11];
    const int* src = ei;
    const int* dst = ei + EE;
    float* out = (float*)d_out;

    const int TB = 256;
    const int MB = (NN + 127) / 128;  // 157
    init_kernel<<<(NN * LD + TB - 1) / TB, TB>>>(s);
    deg_kernel<<<(EE + TB - 1) / TB, TB>>>(dst);
    scan_kernel<<<1, 1024>>>();
    fill_kernel<<<(EE + TB - 1) / TB, TB>>>(src, dst);

    // precompute pre[r] = z_r @ [W1_top | W2_top]
    gemm_kernel<0><<<dim3(MB, 4, 2), 256>>>(W1, W2, pos, Wenc, benc, nullptr);

    for (int it = 0; it < MAXIT; it++) {
        // ab = h @ [W1_bot | W2_bot] + pre[reach]
        gemm_kernel<1><<<dim3(MB, 4), 256>>>(W1 + 128 * 128, W2 + 128 * 128,
                                             nullptr, nullptr, nullptr, nullptr);
        aggregate_kernel<<<NN, 128>>>(bmsg);
        gemm_kernel<2><<<dim3(MB, 2), 256>>>(Wout, nullptr, nullptr, nullptr, nullptr, bout);
        uv_kernel<<<(NN * 32 + TB - 1) / TB, TB>>>(Wdec);
        alpha_kernel<<<(EE + TB - 1) / TB, TB>>>(src, dst, bdec, out + (size_t)it * EE);
    }
    pack_kernel<<<(EE + TB - 1) / TB, TB>>>(dst);
    output_kernel<<<(NN + TB - 1) / TB, TB>>>(src, out + 10ull * EE, out + 10ull * EE + NN);
}

// round 9
// speedup vs baseline: 1.4379x; 1.4379x over previous
#include <cuda_runtime.h>
#include <math.h>

#define NN 20000
#define EE 320000
#define LD 128
#define MAXIT 10

// ---------------- device scratch ----------------
__device__ __align__(16) float g_h[NN * LD];          // hidden state
__device__ __align__(16) float g_ab[NN * 2 * LD];     // [a | b] per node
__device__ __align__(16) float g_agg[NN * LD];        // aggregated messages
__device__ __align__(16) float g_pre[2ull * NN * 2 * LD]; // z_r @ [W1_top|W2_top], r in {0,1}
__device__ __align__(16) float g_u[NN];
__device__ __align__(16) float g_v[NN];
__device__ __align__(16) float g_alpha[EE];
__device__ int g_mx[NN];                              // max alpha bits over incident edges
__device__ unsigned long long g_pack[NN];             // (alpha_bits<<32)|(EE-1-e) max
__device__ int g_deg[NN];
__device__ int g_off[NN];
__device__ int g_cursor[NN];
__device__ int g_csrc[EE];                            // CSR-by-dst source ids

// ---------------- init ----------------
__global__ void init_kernel(const float* __restrict__ s) {
    int idx = blockIdx.x * blockDim.x + threadIdx.x;
    if (idx < NN * LD) g_h[idx] = 0.f;
    if (idx < NN) {
        g_deg[idx] = 0;
        g_mx[idx] = (s[idx] > 0.f) ? 0x3f800000 : 0;  // reach(iter0) = s
        g_pack[idx] = 0ull;
    }
}

// ---------------- CSR build (by dst) ----------------
__global__ void deg_kernel(const int* __restrict__ dst) {
    int e = blockIdx.x * blockDim.x + threadIdx.x;
    if (e < EE) atomicAdd(&g_deg[dst[e]], 1);
}

__global__ void scan_kernel() {  // single block, 1024 threads
    __shared__ int part[1024];
    int t = threadIdx.x;
    const int chunk = (NN + 1023) / 1024;
    int b0 = t * chunk;
    int acc = 0;
    for (int i = 0; i < chunk; i++) {
        int idx = b0 + i;
        if (idx < NN) acc += g_deg[idx];
    }
    part[t] = acc;
    __syncthreads();
    for (int o = 1; o < 1024; o <<= 1) {
        int v = (t >= o) ? part[t - o] : 0;
        __syncthreads();
        part[t] += v;
        __syncthreads();
    }
    int run = (t == 0) ? 0 : part[t - 1];
    for (int i = 0; i < chunk; i++) {
        int idx = b0 + i;
        if (idx < NN) {
            g_off[idx] = run;
            g_cursor[idx] = run;
            run += g_deg[idx];
        }
    }
}

__global__ void fill_kernel(const int* __restrict__ src, const int* __restrict__ dst) {
    int e = blockIdx.x * blockDim.x + threadIdx.x;
    if (e < EE) {
        int p = atomicAdd(&g_cursor[dst[e]], 1);
        g_csrc[p] = src[e];
    }
}

// ---------------- unified scalar-FFMA GEMM (R1-proven inner loop) ----------------
// MODE 0: pre[r] = z_r(pos) @ [W1_top|W2_top]    grid (157,4,2)
// MODE 1: ab = h @ [W1_bot|W2_bot] + pre[reach]  grid (157,4)
// MODE 2: h = relu(agg @ Wout + bout)            grid (157,2)
template <int MODE>
__global__ __launch_bounds__(256) void gemm_kernel(
    const float* __restrict__ B1, const float* __restrict__ B2,
    const float* __restrict__ pos, const float* __restrict__ We,
    const float* __restrict__ be, const float* __restrict__ bias) {
    __shared__ float As[16][132];
    __shared__ float Bs[16][64];
    int m0 = blockIdx.x * 128;
    int j0 = blockIdx.y * 64;
    int r = (MODE == 0) ? (int)blockIdx.z : 0;
    const float* Bptr;
    int jb;
    if (MODE == 2) { Bptr = B1; jb = j0; }
    else if (j0 < 128) { Bptr = B1; jb = j0; }
    else { Bptr = B2; jb = j0 - 128; }
    int t = threadIdx.x, tx = t & 15, ty = t >> 4;
    float c[8][4] = {};

    for (int kt = 0; kt < 128; kt += 16) {
#pragma unroll
        for (int rr = 0; rr < 2; rr++) {
            int f = t + rr * 256;
            int mloc = f >> 2, k4 = (f & 3) * 4;
            int m = m0 + mloc;
            float4 av = make_float4(0.f, 0.f, 0.f, 0.f);
            if (m < NN) {
                if (MODE == 0) {
                    float p = pos[m];
                    float rf = (float)r;
                    float4 w0 = *(const float4*)(We + kt + k4);
                    float4 w1 = *(const float4*)(We + 128 + kt + k4);
                    float4 b0 = *(const float4*)(be + kt + k4);
                    av.x = fmaxf(fmaf(p, w0.x, fmaf(rf, w1.x, b0.x)), 0.f);
                    av.y = fmaxf(fmaf(p, w0.y, fmaf(rf, w1.y, b0.y)), 0.f);
                    av.z = fmaxf(fmaf(p, w0.z, fmaf(rf, w1.z, b0.z)), 0.f);
                    av.w = fmaxf(fmaf(p, w0.w, fmaf(rf, w1.w, b0.w)), 0.f);
                } else if (MODE == 1) {
                    av = *(const float4*)(g_h + (size_t)m * 128 + kt + k4);
                } else {
                    av = *(const float4*)(g_agg + (size_t)m * 128 + kt + k4);
                }
            }
            As[k4 + 0][mloc] = av.x;
            As[k4 + 1][mloc] = av.y;
            As[k4 + 2][mloc] = av.z;
            As[k4 + 3][mloc] = av.w;
        }
        {
            int kk = t >> 4, j4 = (t & 15) * 4;
            *(float4*)&Bs[kk][j4] = *(const float4*)(Bptr + (size_t)(kt + kk) * 128 + jb + j4);
        }
        __syncthreads();
#pragma unroll
        for (int k = 0; k < 16; k++) {
            float4 a0 = *(const float4*)&As[k][ty * 8];
            float4 a1 = *(const float4*)&As[k][ty * 8 + 4];
            float4 b = *(const float4*)&Bs[k][tx * 4];
            float ar[8] = {a0.x, a0.y, a0.z, a0.w, a1.x, a1.y, a1.z, a1.w};
            float br[4] = {b.x, b.y, b.z, b.w};
#pragma unroll
            for (int i = 0; i < 8; i++)
#pragma unroll
                for (int jj = 0; jj < 4; jj++) c[i][jj] = fmaf(ar[i], br[jj], c[i][jj]);
        }
        __syncthreads();
    }

#pragma unroll
    for (int i = 0; i < 8; i++) {
        int m = m0 + ty * 8 + i;
        if (m >= NN) continue;
        int jc = j0 + tx * 4;
        float4 v = make_float4(c[i][0], c[i][1], c[i][2], c[i][3]);
        if (MODE == 0) {
            *(float4*)(g_pre + ((size_t)r * NN + m) * 256 + jc) = v;
        } else if (MODE == 1) {
            int sel = (__int_as_float(g_mx[m]) >= 0.4f) ? 1 : 0;
            float4 pr = *(const float4*)(g_pre + ((size_t)sel * NN + m) * 256 + jc);
            v.x += pr.x; v.y += pr.y; v.z += pr.z; v.w += pr.w;
            *(float4*)(g_ab + (size_t)m * 256 + jc) = v;
        } else {
            float4 bb = *(const float4*)(bias + jc);
            v.x = fmaxf(v.x + bb.x, 0.f);
            v.y = fmaxf(v.y + bb.y, 0.f);
            v.z = fmaxf(v.z + bb.z, 0.f);
            v.w = fmaxf(v.w + bb.w, 0.f);
            *(float4*)(g_h + (size_t)m * 128 + jc) = v;
        }
    }
}

// ---------------- aggregate: agg[n] = relu(max_in a[src] + b[n] + bmsg) ----------------
__global__ void aggregate_kernel(const float* __restrict__ bmsg) {
    int n = blockIdx.x;
    int l = threadIdx.x;
    int beg = g_off[n];
    int d = g_deg[n];
    float out = 0.f;
    if (d > 0) {
        float s = -3.4e38f;
        for (int p = 0; p < d; p++) {
            int sn = g_csrc[beg + p];
            s = fmaxf(s, g_ab[(size_t)sn * 256 + l]);
        }
        out = fmaxf(s + g_ab[(size_t)n * 256 + 128 + l] + bmsg[l], 0.f);
    }
    g_agg[(size_t)n * 128 + l] = out;
}

// ---------------- decoder dots + mx reset ----------------
__global__ void uv_kernel(const float* __restrict__ Wdec) {
    int gt = blockIdx.x * blockDim.x + threadIdx.x;
    int w = gt >> 5, lane = gt & 31;
    if (w >= NN) return;
    float4 hv = ((const float4*)(g_h + (size_t)w * 128))[lane];
    float4 w1 = ((const float4*)Wdec)[lane];
    float4 w2 = ((const float4*)(Wdec + 128))[lane];
    float pu = hv.x * w1.x + hv.y * w1.y + hv.z * w1.z + hv.w * w1.w;
    float pv = hv.x * w2.x + hv.y * w2.y + hv.z * w2.z + hv.w * w2.w;
#pragma unroll
    for (int o = 16; o; o >>= 1) {
        pu += __shfl_down_sync(0xffffffffu, pu, o);
        pv += __shfl_down_sync(0xffffffffu, pv, o);
    }
    if (lane == 0) {
        g_u[w] = pu;
        g_v[w] = pv;
        g_mx[w] = 0;  // reset for this iteration's alpha pass
    }
}

// ---------------- edge alpha + incident-max ----------------
__global__ void alpha_kernel(const int* __restrict__ src, const int* __restrict__ dst,
                             const float* __restrict__ bdec, float* __restrict__ preds_out) {
    int e = blockIdx.x * blockDim.x + threadIdx.x;
    if (e >= EE) return;
    int sn = src[e], dn = dst[e];
    float x = g_u[sn] + g_v[dn] + bdec[0];
    float al = 1.f / (1.f + expf(-x));
    preds_out[e] = al;
    g_alpha[e] = al;
    int bits = __float_as_int(al);  // al >= 0, bit order == float order
    atomicMax(&g_mx[sn], bits);
    atomicMax(&g_mx[dn], bits);
}

// ---------------- parents: single packed atomicMax pass ----------------
__global__ void pack_kernel(const int* __restrict__ dst) {
    int e = blockIdx.x * blockDim.x + threadIdx.x;
    if (e >= EE) return;
    unsigned long long p =
        ((unsigned long long)(unsigned)__float_as_int(g_alpha[e]) << 32) |
        (unsigned)(EE - 1 - e);  // tie -> larger low bits -> smaller e (first occurrence)
    atomicMax(&g_pack[dst[e]], p);
}

__global__ void output_kernel(const int* __restrict__ src, float* __restrict__ out_reach,
                              float* __restrict__ out_par) {
    int n = blockIdx.x * blockDim.x + threadIdx.x;
    if (n >= NN) return;
    out_reach[n] = (__int_as_float(g_mx[n]) >= 0.4f) ? 1.f : 0.f;
    unsigned long long p = g_pack[n];
    if (p != 0ull) {
        int e = EE - 1 - (int)(p & 0xffffffffu);
        out_par[n] = (float)src[e];
    } else {
        out_par[n] = (float)n;
    }
}

// ---------------- launch ----------------
extern "C" void kernel_launch(void* const* d_in, const int* in_sizes, int n_in,
                              void* d_out, int out_size) {
    const float* pos  = (const float*)d_in[0];
    const float* s    = (const float*)d_in[1];
    const int*   ei   = (const int*)d_in[2];
    const float* Wenc = (const float*)d_in[3];
    const float* benc = (const float*)d_in[4];
    const float* W1   = (const float*)d_in[5];
    const float* W2   = (const float*)d_in[6];
    const float* bmsg = (const float*)d_in[7];
    const float* Wout = (const float*)d_in[8];
    const float* bout = (const float*)d_in[9];
    const float* Wdec = (const float*)d_in[10];
    const float* bdec = (const float*)d_in[11];
    const int* src = ei;
    const int* dst = ei + EE;
    float* out = (float*)d_out;

    const int TB = 256;
    const int MB = (NN + 127) / 128;  // 157
    init_kernel<<<(NN * LD + TB - 1) / TB, TB>>>(s);
    deg_kernel<<<(EE + TB - 1) / TB, TB>>>(dst);
    scan_kernel<<<1, 1024>>>();
    fill_kernel<<<(EE + TB - 1) / TB, TB>>>(src, dst);

    // precompute pre[r] = z_r @ [W1_top | W2_top]
    gemm_kernel<0><<<dim3(MB, 4, 2), 256>>>(W1, W2, pos, Wenc, benc, nullptr);

    for (int it = 0; it < MAXIT; it++) {
        // ab = h @ [W1_bot | W2_bot] + pre[reach]
        gemm_kernel<1><<<dim3(MB, 4), 256>>>(W1 + 128 * 128, W2 + 128 * 128,
                                             nullptr, nullptr, nullptr, nullptr);
        aggregate_kernel<<<NN, 128>>>(bmsg);
        gemm_kernel<2><<<dim3(MB, 2), 256>>>(Wout, nullptr, nullptr, nullptr, nullptr, bout);
        uv_kernel<<<(NN * 32 + TB - 1) / TB, TB>>>(Wdec);
        alpha_kernel<<<(EE + TB - 1) / TB, TB>>>(src, dst, bdec, out + (size_t)it * EE);
    }
    pack_kernel<<<(EE + TB - 1) / TB, TB>>>(dst);
    output_kernel<<<(NN + TB - 1) / TB, TB>>>(src, out + 10ull * EE, out + 10ull * EE + NN);
}